// round 7
// baseline (speedup 1.0000x reference)
#include <cuda_runtime.h>

// ---------------------------------------------------------------------------
// RNN_70480413327462: 59-step patch-grid RNN + 9-neighbor center attention.
// R6: R2 compute structure (1 warp = 1 patch, both batches) with the global
// grid barrier replaced by LOCAL producer/consumer epoch flags: each warp
// waits only on the <=7 CTAs producing its neighbors (RAW) and <=11 CTAs
// consuming its rows (WAR, double buffer). One __syncthreads per CTA/step.
// ---------------------------------------------------------------------------

#define NBLK   148
#define NTHR   896
#define NWARPS 28
#define PP     4096
#define NROWS  8192
#define HH     32
#define TSTEPS 59
#define NOBS   10
#define KPAD   36
#define INV_SQRT_E 0.1714985851425088f   // 1/sqrt(34)

// double-buffered Q/K/V scratch (step parity), padded rows of 36 floats
__device__ float g_Q[2][NROWS * KPAD];
__device__ float g_K[2][NROWS * KPAD];
__device__ float g_V[2][NROWS * KPAD];
// per-CTA epoch flags (monotonic across launches; device globals zero-init)
__device__ volatile unsigned g_prodF[160];
__device__ volatile unsigned g_consF[160];

struct Smem {
    float4 Wc[32][17];        // c<8: W_x2h chunk c; c>=8: W_h2h chunk c-8
    float4 Wq[32][9];
    float4 Wk[32][9];
    float4 Wv[32][9];
    float4 Mw[32][9];         // (W_fcsa@W_out)^T chunks (9 used, tail zeroed)
    float4 Wf[32][9];         // W_fc2 chunks (8 used)
    float4 We[6][9];          // ext rows (q32,q33,k32,k33,v32,v33)
    float4 RB[NWARPS][2][17]; // per-warp stage: [0..8] inp/ht/o, [9..16] h
    int    NBS[NWARPS][12];   // 9 neighbor row-offsets (elements)
    unsigned bp, bc;          // flag bases for this launch
};

__device__ __forceinline__ float warpAllSum(float v) {
#pragma unroll
    for (int o = 16; o > 0; o >>= 1) v += __shfl_xor_sync(0xffffffffu, v, o);
    return v;
}

__device__ __forceinline__ float ftanh(float x) {
    float e = __expf(2.f * x);
    return 1.f - __fdividef(2.f, e + 1.f);
}

__device__ __forceinline__ float dot4(float4 a, float4 b) {
    return fmaf(a.x, b.x, fmaf(a.y, b.y, fmaf(a.z, b.z, a.w * b.w)));
}

extern __shared__ unsigned char smem_raw[];

__global__ void __launch_bounds__(NTHR, 1) rnn_kernel(
    const float* __restrict__ x,
    const float* __restrict__ W_x2h, const float* __restrict__ b_x2h,
    const float* __restrict__ W_h2h, const float* __restrict__ b_h2h,
    const float* __restrict__ W_fc2, const float* __restrict__ b_fc2,
    const float* __restrict__ ln_g,  const float* __restrict__ ln_b,
    const float* __restrict__ W_fcsa,const float* __restrict__ b_fcsa,
    const float* __restrict__ W_in,  const float* __restrict__ b_in,
    const float* __restrict__ W_out, const float* __restrict__ b_out,
    float* __restrict__ out)
{
    Smem* sm = reinterpret_cast<Smem*>(smem_raw);
    const int tid = threadIdx.x;

    // ---------------- smem weight init ----------------
    for (int idx = tid; idx < 32 * 16; idx += NTHR) {
        int e = idx >> 4, c = idx & 15;
        const float* src = (c < 8) ? (W_x2h + e * 32 + c * 4)
                                   : (W_h2h + e * 32 + (c - 8) * 4);
        sm->Wc[e][c] = make_float4(src[0], src[1], src[2], src[3]);
    }
    for (int idx = tid; idx < 32 * 8; idx += NTHR) {
        int e = idx >> 3, c = idx & 7, i = c * 4;
        const float* q = W_in + e * 34 + i;
        const float* k = W_in + (34 + e) * 34 + i;
        const float* v = W_in + (68 + e) * 34 + i;
        const float* f = W_fc2 + e * 32 + i;
        sm->Wq[e][c] = make_float4(q[0], q[1], q[2], q[3]);
        sm->Wk[e][c] = make_float4(k[0], k[1], k[2], k[3]);
        sm->Wv[e][c] = make_float4(v[0], v[1], v[2], v[3]);
        sm->Wf[e][c] = make_float4(f[0], f[1], f[2], f[3]);
    }
    for (int idx = tid; idx < 32 * 9; idx += NTHR) {
        int e = idx / 9, c = idx % 9;
        float w[4];
#pragma unroll
        for (int d = 0; d < 4; d++) {
            int f = c * 4 + d;
            float acc = 0.f;
            if (f < 34)
                for (int g = 0; g < 34; g++)
                    acc += W_fcsa[e * 34 + g] * W_out[g * 34 + f];
            w[d] = acc;
        }
        sm->Mw[e][c] = make_float4(w[0], w[1], w[2], w[3]);
    }
    for (int idx = tid; idx < 6 * 8; idx += NTHR) {
        int j = idx >> 3, c = idx & 7;
        int row = (j >> 1) * 34 + 32 + (j & 1);
        const float* src = W_in + row * 34 + c * 4;
        sm->We[j][c] = make_float4(src[0], src[1], src[2], src[3]);
    }
    if (tid == 0) {
        sm->bp = g_prodF[blockIdx.x];   // only this CTA writes these flags
        sm->bc = g_consF[blockIdx.x];
    }

    const int lane = tid & 31;
    const int wid  = tid >> 5;
    const int p    = blockIdx.x * NWARPS + wid;
    const bool active = (p < PP);

    // ---------------- per-lane constants ----------------
    int pqOff = 0;
    float bql = 0.f, bkl = 0.f, bvl = 0.f;
    float bcombL = 0.f, bfL = 0.f, lngL = 0.f, lnbL = 0.f, bbL = 0.f;
    float exC = 0.f;
    int   eoff = 0;
    const int sRow = lane >> 4;
    const int sM   = lane & 15;
    const bool sAct = (sM < 9);
    const bool eAct = (sM < 6);

    int prodLo = 0, prodSpan = -1, consLo = 0, consSpan = -1;

    if (active) {
        int r = p >> 6, cI = p & 63;
        float c0 = (float)r  * (1.f / 64.f);
        float c1 = (float)cI * (1.f / 64.f);
        int rc  = min(max(r, 1), 62);
        int ccn = min(max(cI, 1), 62);
        pqOff = (rc * 64 + ccn) * KPAD;
        if (lane < 9)
            sm->NBS[wid][lane] = ((rc + lane / 3 - 1) * 64 + (ccn + lane % 3 - 1)) * KPAD;

        // flag windows (warp-uniform)
        {
            int minNb = (rc - 1) * 64 + (ccn - 1);
            int maxNb = (rc + 1) * 64 + (ccn + 1);
            prodLo = minNb / NWARPS;
            prodSpan = maxNb / NWARPS - prodLo;
            int cmin = max(p - 130, 0);
            int cmax = min(p + 130, PP - 1);
            consLo = cmin / NWARPS;
            consSpan = cmax / NWARPS - consLo;
        }

        bql = b_in[lane]      + c0 * W_in[lane * 34 + 32]      + c1 * W_in[lane * 34 + 33];
        bkl = b_in[34 + lane] + c0 * W_in[(34 + lane) * 34 + 32] + c1 * W_in[(34 + lane) * 34 + 33];
        bvl = b_in[68 + lane] + c0 * W_in[(68 + lane) * 34 + 32] + c1 * W_in[(68 + lane) * 34 + 33];
        bcombL = b_x2h[lane] + b_h2h[lane];
        bfL  = b_fc2[lane];
        lngL = ln_g[lane];
        lnbL = ln_b[lane];
        {
            float acc = b_fcsa[lane];
            for (int g = 0; g < 34; g++) acc += b_out[g] * W_fcsa[lane * 34 + g];
            bbL = acc;
        }
        if (eAct) {
            int j = sM;
            int row = (j >> 1) * 34 + 32 + (j & 1);
            exC = b_in[row] + c0 * W_in[row * 34 + 32] + c1 * W_in[row * 34 + 33];
            eoff = ((sRow ? PP + p : p)) * KPAD + 32 + (j & 1);
        }
        // zero h staging + QKV row pads (elements 34,35) once
        ((float*)sm->RB[wid][0])[36 + lane] = 0.f;
        ((float*)sm->RB[wid][1])[36 + lane] = 0.f;
        if (lane < 2) {
#pragma unroll
            for (int par = 0; par < 2; par++) {
#pragma unroll
                for (int row = 0; row < 2; row++) {
                    size_t o = (size_t)(row * PP + p) * KPAD + 34 + lane;
                    g_Q[par][o] = 0.f; g_K[par][o] = 0.f; g_V[par][o] = 0.f;
                }
            }
        }
    }
    __syncthreads();

    const unsigned bp = sm->bp;
    const unsigned bc = sm->bc;
    int nbBase = (active && sAct) ? sm->NBS[wid][sM] : 0;
    const int rowAdd = sRow * PP * KPAD;
    const int kOffR  = nbBase + rowAdd;
    const int qOffR  = pqOff + rowAdd;
    const int r0Off  = p * KPAD + lane;
    const int r1Off  = (PP + p) * KPAD + lane;

    float4* RB0 = sm->RB[wid][0];
    float4* RB1 = sm->RB[wid][1];
    float*  RB0f = (float*)RB0;
    float*  RB1f = (float*)RB1;

    float h0 = 0.f, h1 = 0.f, ht0 = 0.f, ht1 = 0.f;

    for (int t = 0; t < TSTEPS; t++) {
        const int buf = t & 1;
        float* Qb = g_Q[buf];
        float* Kb = g_K[buf];
        float* Vb = g_V[buf];

        // =============== WAR wait: consumers done with step t-2 ===============
        if (active) {
            if (lane <= consSpan) {
                unsigned want = bc + (unsigned)t - 1u;   // g_cons >= bc + t - 1
                const volatile unsigned* f = &g_consF[consLo + lane];
                while ((int)(*f - want) < 0) __nanosleep(32);
            }
            __syncwarp();

            // =============== PHASE 1: RNN cell + QKV produce ===============
            if (t < NOBS) {
                RB0f[lane] = x[((size_t)t * NROWS + p) * HH + lane];
                RB1f[lane] = x[((size_t)t * NROWS + PP + p) * HH + lane];
            }
            __syncwarp();

            float a0 = bcombL, a1 = bcombL;
#pragma unroll
            for (int c = 0; c < 16; c++) {
                float4 w  = sm->Wc[lane][c];
                int dc = (c < 8) ? c : c + 1;     // h lives at chunks 9..16
                a0 += dot4(RB0[dc], w);
                a1 += dot4(RB1[dc], w);
            }
            ht0 = ftanh(a0);
            ht1 = ftanh(a1);

            __syncwarp();
            RB0f[lane] = ht0;    // stage ht in chunks 0..7 (overwrites inp)
            RB1f[lane] = ht1;
            __syncwarp();

            float q0 = bql, k0 = bkl, v0 = bvl;
            float q1 = bql, k1 = bkl, v1 = bvl;
#pragma unroll
            for (int c = 0; c < 8; c++) {
                float4 wq = sm->Wq[lane][c];
                float4 wk = sm->Wk[lane][c];
                float4 wv = sm->Wv[lane][c];
                float4 t0 = RB0[c];
                float4 t1 = RB1[c];
                q0 += dot4(t0, wq); k0 += dot4(t0, wk); v0 += dot4(t0, wv);
                q1 += dot4(t1, wq); k1 += dot4(t1, wk); v1 += dot4(t1, wv);
            }
            Qb[r0Off] = q0; Kb[r0Off] = k0; Vb[r0Off] = v0;
            Qb[r1Off] = q1; Kb[r1Off] = k1; Vb[r1Off] = v1;

            if (eAct) {
                const float4* htp = sRow ? RB1 : RB0;
                float ex = exC;
#pragma unroll
                for (int c = 0; c < 8; c++)
                    ex += dot4(htp[c], sm->We[sM][c]);
                float* eb = (sM < 2) ? Qb : ((sM < 4) ? Kb : Vb);
                eb[eoff] = ex;
            }
        }

        // =============== publish: prod(t) ready, cons(t-1) done ===============
        __threadfence();          // release own QKV stores; order phase2(t-1) loads
        __syncthreads();          // all warps of CTA reached here
        if (tid == 0) {
            g_prodF[blockIdx.x] = bp + (unsigned)t + 1u;
            g_consF[blockIdx.x] = bc + (unsigned)t;
        }

        // =============== RAW wait: neighbor producers at step t ===============
        if (active) {
            if (lane <= prodSpan) {
                unsigned want = bp + (unsigned)t + 1u;
                const volatile unsigned* f = &g_prodF[prodLo + lane];
                while ((int)(*f - want) < 0) __nanosleep(32);
            }
            __syncwarp();
            __threadfence();      // acquire: order flag observation before data loads

            // =============== PHASE 2: attention + update + pred ===============
            float sc = -3.4e38f;
            if (sAct) {
                const float4* qrow = (const float4*)(Qb + qOffR);
                const float4* krow = (const float4*)(Kb + kOffR);
                float d = 0.f;
#pragma unroll
                for (int c = 0; c < 9; c++) {
                    float4 qc = __ldcg(qrow + c);
                    float4 kc = __ldcg(krow + c);
                    d += dot4(qc, kc);
                }
                sc = d;
            }
            float mx = sc;
#pragma unroll
            for (int o = 8; o > 0; o >>= 1)
                mx = fmaxf(mx, __shfl_xor_sync(0xffffffffu, mx, o, 16));
            float ew = __expf((sc - mx) * INV_SQRT_E);
            float ssum = ew;
#pragma unroll
            for (int o = 8; o > 0; o >>= 1)
                ssum += __shfl_xor_sync(0xffffffffu, ssum, o, 16);
            float wgt = ew * __fdividef(1.f, ssum);

            float4 o4 = make_float4(0.f, 0.f, 0.f, 0.f);
#pragma unroll
            for (int m = 0; m < 9; m++) {
                float wm = __shfl_sync(0xffffffffu, wgt, m, 16);
                int   nm = __shfl_sync(0xffffffffu, nbBase, m, 16);
                if (sAct) {
                    float4 vv = __ldcg((const float4*)(Vb + nm + rowAdd) + sM);
                    o4.x = fmaf(wm, vv.x, o4.x);
                    o4.y = fmaf(wm, vv.y, o4.y);
                    o4.z = fmaf(wm, vv.z, o4.z);
                    o4.w = fmaf(wm, vv.w, o4.w);
                }
            }
            if (sAct) (sRow ? RB1 : RB0)[sM] = o4;   // o chunks 0..8
            __syncwarp();

            // --- fused out-proj + fcsa: h = ht + o @ M^T + bb ---
            float d0 = bbL, d1 = bbL;
#pragma unroll
            for (int c = 0; c < 9; c++) {
                float4 wt = sm->Mw[lane][c];
                d0 += dot4(RB0[c], wt);
                d1 += dot4(RB1[c], wt);
            }
            h0 = ht0 + d0;
            h1 = ht1 + d1;

            RB0f[36 + lane] = h0;   // h chunks 9..16
            RB1f[36 + lane] = h1;
            __syncwarp();

            // --- fc2 + layernorm -> pred ---
            float y0 = bfL, y1 = bfL;
#pragma unroll
            for (int c = 0; c < 8; c++) {
                float4 wt = sm->Wf[lane][c];
                y0 += dot4(RB0[9 + c], wt);
                y1 += dot4(RB1[9 + c], wt);
            }
            float m0 = warpAllSum(y0) * (1.f / 32.f);
            float dd0 = y0 - m0;
            float var0 = warpAllSum(dd0 * dd0) * (1.f / 32.f);
            float pred0 = dd0 * rsqrtf(var0 + 1e-5f) * lngL + lnbL;
            float m1 = warpAllSum(y1) * (1.f / 32.f);
            float dd1 = y1 - m1;
            float var1 = warpAllSum(dd1 * dd1) * (1.f / 32.f);
            float pred1 = dd1 * rsqrtf(var1 + 1e-5f) * lngL + lnbL;

            RB0f[lane] = pred0;     // stage as next-step input (chunks 0..7)
            RB1f[lane] = pred1;

            out[((size_t)t * NROWS + p) * HH + lane]      = pred0;
            out[((size_t)t * NROWS + PP + p) * HH + lane] = pred1;
        }
    }
}

extern "C" void kernel_launch(void* const* d_in, const int* in_sizes, int n_in,
                              void* d_out, int out_size) {
    (void)in_sizes; (void)n_in; (void)out_size;
    cudaFuncSetAttribute(rnn_kernel, cudaFuncAttributeMaxDynamicSharedMemorySize,
                         (int)sizeof(Smem));
    rnn_kernel<<<NBLK, NTHR, sizeof(Smem)>>>(
        (const float*)d_in[0],
        (const float*)d_in[1],  (const float*)d_in[2],
        (const float*)d_in[3],  (const float*)d_in[4],
        (const float*)d_in[5],  (const float*)d_in[6],
        (const float*)d_in[7],  (const float*)d_in[8],
        (const float*)d_in[9],  (const float*)d_in[10],
        (const float*)d_in[11], (const float*)d_in[12],
        (const float*)d_in[13], (const float*)d_in[14],
        (float*)d_out);
}

// round 8
// speedup vs baseline: 2.0216x; 2.0216x over previous
#include <cuda_runtime.h>

// ---------------------------------------------------------------------------
// RNN_70480413327462: 59-step patch-grid RNN + 9-neighbor center attention.
// R7: R2 compute structure (best: 748us) + hierarchical 2-level grid barrier
// (16 padded leaf counters -> root -> single release word, bare spin).
// ---------------------------------------------------------------------------

#define NBLK   148
#define NTHR   896
#define NWARPS 28
#define PP     4096
#define NROWS  8192
#define HH     32
#define TSTEPS 59
#define NOBS   10
#define KPAD   36
#define INV_SQRT_E 0.1714985851425088f   // 1/sqrt(34)

// double-buffered Q/K/V scratch (step parity), padded rows of 36 floats
__device__ float g_Q[2][NROWS * KPAD];
__device__ float g_K[2][NROWS * KPAD];
__device__ float g_V[2][NROWS * KPAD];
// hierarchical barrier state (monotonic epochs, zero-init)
__device__ unsigned g_leaf[16 * 32];     // one counter per 128B line
__device__ unsigned g_root = 0;
__device__ volatile unsigned g_gen = 0;

struct Smem {
    float4 Wc[32][17];        // c<8: W_x2h chunk c; c>=8: W_h2h chunk c-8
    float4 Wq[32][9];
    float4 Wk[32][9];
    float4 Wv[32][9];
    float4 Mw[32][9];         // (W_fcsa@W_out)^T chunks (9 used, tail zeroed)
    float4 Wf[32][9];         // W_fc2 chunks (8 used)
    float4 We[6][9];          // ext rows (q32,q33,k32,k33,v32,v33)
    float4 RB[NWARPS][2][17]; // per-warp stage: [0..8] inp/ht/o, [9..16] h
    int    NBS[NWARPS][12];   // 9 neighbor row-offsets (elements)
    unsigned sbase;
};

__device__ __forceinline__ float warpAllSum(float v) {
#pragma unroll
    for (int o = 16; o > 0; o >>= 1) v += __shfl_xor_sync(0xffffffffu, v, o);
    return v;
}

__device__ __forceinline__ float ftanh(float x) {
    float e = __expf(2.f * x);
    return 1.f - __fdividef(2.f, e + 1.f);
}

__device__ __forceinline__ float dot4(float4 a, float4 b) {
    return fmaf(a.x, b.x, fmaf(a.y, b.y, fmaf(a.z, b.z, a.w * b.w)));
}

extern __shared__ unsigned char smem_raw[];

__global__ void __launch_bounds__(NTHR, 1) rnn_kernel(
    const float* __restrict__ x,
    const float* __restrict__ W_x2h, const float* __restrict__ b_x2h,
    const float* __restrict__ W_h2h, const float* __restrict__ b_h2h,
    const float* __restrict__ W_fc2, const float* __restrict__ b_fc2,
    const float* __restrict__ ln_g,  const float* __restrict__ ln_b,
    const float* __restrict__ W_fcsa,const float* __restrict__ b_fcsa,
    const float* __restrict__ W_in,  const float* __restrict__ b_in,
    const float* __restrict__ W_out, const float* __restrict__ b_out,
    float* __restrict__ out)
{
    Smem* sm = reinterpret_cast<Smem*>(smem_raw);
    const int tid = threadIdx.x;

    // ---------------- smem weight init ----------------
    for (int idx = tid; idx < 32 * 16; idx += NTHR) {
        int e = idx >> 4, c = idx & 15;
        const float* src = (c < 8) ? (W_x2h + e * 32 + c * 4)
                                   : (W_h2h + e * 32 + (c - 8) * 4);
        sm->Wc[e][c] = make_float4(src[0], src[1], src[2], src[3]);
    }
    for (int idx = tid; idx < 32 * 8; idx += NTHR) {
        int e = idx >> 3, c = idx & 7, i = c * 4;
        const float* q = W_in + e * 34 + i;
        const float* k = W_in + (34 + e) * 34 + i;
        const float* v = W_in + (68 + e) * 34 + i;
        const float* f = W_fc2 + e * 32 + i;
        sm->Wq[e][c] = make_float4(q[0], q[1], q[2], q[3]);
        sm->Wk[e][c] = make_float4(k[0], k[1], k[2], k[3]);
        sm->Wv[e][c] = make_float4(v[0], v[1], v[2], v[3]);
        sm->Wf[e][c] = make_float4(f[0], f[1], f[2], f[3]);
    }
    for (int idx = tid; idx < 32 * 9; idx += NTHR) {
        int e = idx / 9, c = idx % 9;
        float w[4];
#pragma unroll
        for (int d = 0; d < 4; d++) {
            int f = c * 4 + d;
            float acc = 0.f;
            if (f < 34)
                for (int g = 0; g < 34; g++)
                    acc += W_fcsa[e * 34 + g] * W_out[g * 34 + f];
            w[d] = acc;
        }
        sm->Mw[e][c] = make_float4(w[0], w[1], w[2], w[3]);
    }
    for (int idx = tid; idx < 6 * 8; idx += NTHR) {
        int j = idx >> 3, c = idx & 7;
        int row = (j >> 1) * 34 + 32 + (j & 1);
        const float* src = W_in + row * 34 + c * 4;
        sm->We[j][c] = make_float4(src[0], src[1], src[2], src[3]);
    }
    if (tid == 0) sm->sbase = g_gen;   // safe: no release before all CTAs arrive

    const int lane = tid & 31;
    const int wid  = tid >> 5;
    const int p    = blockIdx.x * NWARPS + wid;
    const bool active = (p < PP);

    // barrier group constants
    const unsigned grp      = blockIdx.x & 15u;
    const unsigned gMembers = 9u + (grp < 4u ? 1u : 0u);   // 148 = 4*10 + 12*9

    // ---------------- per-lane constants ----------------
    int pqOff = 0;
    float bql = 0.f, bkl = 0.f, bvl = 0.f;
    float bcombL = 0.f, bfL = 0.f, lngL = 0.f, lnbL = 0.f, bbL = 0.f;
    float exC = 0.f;
    int   eoff = 0;
    const int sRow = lane >> 4;           // attention half: 0->batch0, 1->batch1
    const int sM   = lane & 15;           // per-half index
    const bool sAct = (sM < 9);
    const bool eAct = (sM < 6);

    if (active) {
        int r = p >> 6, cI = p & 63;
        float c0 = (float)r  * (1.f / 64.f);
        float c1 = (float)cI * (1.f / 64.f);
        int rc  = min(max(r, 1), 62);
        int ccn = min(max(cI, 1), 62);
        pqOff = (rc * 64 + ccn) * KPAD;
        if (lane < 9)
            sm->NBS[wid][lane] = ((rc + lane / 3 - 1) * 64 + (ccn + lane % 3 - 1)) * KPAD;

        bql = b_in[lane]      + c0 * W_in[lane * 34 + 32]      + c1 * W_in[lane * 34 + 33];
        bkl = b_in[34 + lane] + c0 * W_in[(34 + lane) * 34 + 32] + c1 * W_in[(34 + lane) * 34 + 33];
        bvl = b_in[68 + lane] + c0 * W_in[(68 + lane) * 34 + 32] + c1 * W_in[(68 + lane) * 34 + 33];
        bcombL = b_x2h[lane] + b_h2h[lane];
        bfL  = b_fc2[lane];
        lngL = ln_g[lane];
        lnbL = ln_b[lane];
        {
            float acc = b_fcsa[lane];
            for (int g = 0; g < 34; g++) acc += b_out[g] * W_fcsa[lane * 34 + g];
            bbL = acc;
        }
        if (eAct) {
            int j = sM;
            int row = (j >> 1) * 34 + 32 + (j & 1);
            exC = b_in[row] + c0 * W_in[row * 34 + 32] + c1 * W_in[row * 34 + 33];
            eoff = ((sRow ? PP + p : p)) * KPAD + 32 + (j & 1);
        }
        // zero h staging + QKV row pads (elements 34,35) once
        ((float*)sm->RB[wid][0])[36 + lane] = 0.f;
        ((float*)sm->RB[wid][1])[36 + lane] = 0.f;
        if (lane < 2) {
#pragma unroll
            for (int par = 0; par < 2; par++) {
#pragma unroll
                for (int row = 0; row < 2; row++) {
                    size_t o = (size_t)(row * PP + p) * KPAD + 34 + lane;
                    g_Q[par][o] = 0.f; g_K[par][o] = 0.f; g_V[par][o] = 0.f;
                }
            }
        }
    }
    __syncthreads();

    const unsigned sbase = sm->sbase;
    int nbBase = (active && sAct) ? sm->NBS[wid][sM] : 0;
    const int rowAdd = sRow * PP * KPAD;
    const int kOffR  = nbBase + rowAdd;
    const int qOffR  = pqOff + rowAdd;
    const int r0Off  = p * KPAD + lane;
    const int r1Off  = (PP + p) * KPAD + lane;

    float4* RB0 = sm->RB[wid][0];
    float4* RB1 = sm->RB[wid][1];
    float*  RB0f = (float*)RB0;
    float*  RB1f = (float*)RB1;

    float h0 = 0.f, h1 = 0.f, ht0 = 0.f, ht1 = 0.f;

    for (int t = 0; t < TSTEPS; t++) {
        const int buf = t & 1;
        float* Qb = g_Q[buf];
        float* Kb = g_K[buf];
        float* Vb = g_V[buf];

        // =============== PHASE 1: RNN cell + QKV produce ===============
        if (active) {
            if (t < NOBS) {   // stage external input (else pred already staged)
                RB0f[lane] = x[((size_t)t * NROWS + p) * HH + lane];
                RB1f[lane] = x[((size_t)t * NROWS + PP + p) * HH + lane];
            }
            __syncwarp();

            float a0 = bcombL, a1 = bcombL;
#pragma unroll
            for (int c = 0; c < 16; c++) {
                float4 w  = sm->Wc[lane][c];
                int dc = (c < 8) ? c : c + 1;     // h lives at chunks 9..16
                a0 += dot4(RB0[dc], w);
                a1 += dot4(RB1[dc], w);
            }
            ht0 = ftanh(a0);
            ht1 = ftanh(a1);

            __syncwarp();
            RB0f[lane] = ht0;    // stage ht in chunks 0..7 (overwrites inp)
            RB1f[lane] = ht1;
            __syncwarp();

            float q0 = bql, k0 = bkl, v0 = bvl;
            float q1 = bql, k1 = bkl, v1 = bvl;
#pragma unroll
            for (int c = 0; c < 8; c++) {
                float4 wq = sm->Wq[lane][c];
                float4 wk = sm->Wk[lane][c];
                float4 wv = sm->Wv[lane][c];
                float4 t0 = RB0[c];
                float4 t1 = RB1[c];
                q0 += dot4(t0, wq); k0 += dot4(t0, wk); v0 += dot4(t0, wv);
                q1 += dot4(t1, wq); k1 += dot4(t1, wk); v1 += dot4(t1, wv);
            }
            Qb[r0Off] = q0; Kb[r0Off] = k0; Vb[r0Off] = v0;
            Qb[r1Off] = q1; Kb[r1Off] = k1; Vb[r1Off] = v1;

            // extra elements e=32,33 of q/k/v: lanes 0-5 row0, 16-21 row1
            if (eAct) {
                const float4* htp = sRow ? RB1 : RB0;
                float ex = exC;
#pragma unroll
                for (int c = 0; c < 8; c++)
                    ex += dot4(htp[c], sm->We[sM][c]);
                float* eb = (sM < 2) ? Qb : ((sM < 4) ? Kb : Vb);
                eb[eoff] = ex;
            }
        }

        // =============== HIERARCHICAL GRID BARRIER (one per step) ===============
        {
            __threadfence();
            __syncthreads();
            if (tid == 0) {
                unsigned want = sbase + (unsigned)t + 1u;
                unsigned tk = atomicAdd(&g_leaf[grp * 32u], 1u);
                if ((tk % gMembers) == gMembers - 1u) {
                    unsigned rk = atomicAdd(&g_root, 1u);
                    if ((rk & 15u) == 15u)
                        g_gen = want;                    // single releaser
                }
                while ((int)(g_gen - want) < 0) { }      // bare spin on shared line
            }
            __syncthreads();
            __threadfence();
        }

        // =============== PHASE 2: attention gather + update + pred ===============
        if (active) {
            // --- scores: lane m of each half computes q . k_nb[m] over 36 ---
            float sc = -3.4e38f;
            if (sAct) {
                const float4* qrow = (const float4*)(Qb + qOffR);
                const float4* krow = (const float4*)(Kb + kOffR);
                float d = 0.f;
#pragma unroll
                for (int c = 0; c < 9; c++) {
                    float4 qc = __ldcg(qrow + c);
                    float4 kc = __ldcg(krow + c);
                    d += dot4(qc, kc);
                }
                sc = d;
            }
            // group softmax over 9 within each 16-lane half
            float mx = sc;
#pragma unroll
            for (int o = 8; o > 0; o >>= 1)
                mx = fmaxf(mx, __shfl_xor_sync(0xffffffffu, mx, o, 16));
            float ew = __expf((sc - mx) * INV_SQRT_E);
            float ssum = ew;
#pragma unroll
            for (int o = 8; o > 0; o >>= 1)
                ssum += __shfl_xor_sync(0xffffffffu, ssum, o, 16);
            float wgt = ew * __fdividef(1.f, ssum);

            // --- V mix: lane c of each half accumulates o-chunk c ---
            float4 o4 = make_float4(0.f, 0.f, 0.f, 0.f);
#pragma unroll
            for (int m = 0; m < 9; m++) {
                float wm = __shfl_sync(0xffffffffu, wgt, m, 16);
                int   nm = __shfl_sync(0xffffffffu, nbBase, m, 16);
                if (sAct) {
                    float4 vv = __ldcg((const float4*)(Vb + nm + rowAdd) + sM);
                    o4.x = fmaf(wm, vv.x, o4.x);
                    o4.y = fmaf(wm, vv.y, o4.y);
                    o4.z = fmaf(wm, vv.z, o4.z);
                    o4.w = fmaf(wm, vv.w, o4.w);
                }
            }
            if (sAct) (sRow ? RB1 : RB0)[sM] = o4;   // o chunks 0..8
            __syncwarp();

            // --- fused out-proj + fcsa: h = ht + o @ M^T + bb ---
            float d0 = bbL, d1 = bbL;
#pragma unroll
            for (int c = 0; c < 9; c++) {
                float4 wt = sm->Mw[lane][c];
                d0 += dot4(RB0[c], wt);
                d1 += dot4(RB1[c], wt);
            }
            h0 = ht0 + d0;
            h1 = ht1 + d1;

            // stage h (chunks 9..16) for fc2 + next-step RNN
            RB0f[36 + lane] = h0;
            RB1f[36 + lane] = h1;
            __syncwarp();

            // --- fc2 + layernorm -> pred ---
            float y0 = bfL, y1 = bfL;
#pragma unroll
            for (int c = 0; c < 8; c++) {
                float4 wt = sm->Wf[lane][c];
                y0 += dot4(RB0[9 + c], wt);
                y1 += dot4(RB1[9 + c], wt);
            }
            float m0 = warpAllSum(y0) * (1.f / 32.f);
            float dd0 = y0 - m0;
            float var0 = warpAllSum(dd0 * dd0) * (1.f / 32.f);
            float pred0 = dd0 * rsqrtf(var0 + 1e-5f) * lngL + lnbL;
            float m1 = warpAllSum(y1) * (1.f / 32.f);
            float dd1 = y1 - m1;
            float var1 = warpAllSum(dd1 * dd1) * (1.f / 32.f);
            float pred1 = dd1 * rsqrtf(var1 + 1e-5f) * lngL + lnbL;

            // stage pred as next-step input (chunks 0..7)
            RB0f[lane] = pred0;
            RB1f[lane] = pred1;

            out[((size_t)t * NROWS + p) * HH + lane]      = pred0;
            out[((size_t)t * NROWS + PP + p) * HH + lane] = pred1;
        }
    }
}

extern "C" void kernel_launch(void* const* d_in, const int* in_sizes, int n_in,
                              void* d_out, int out_size) {
    (void)in_sizes; (void)n_in; (void)out_size;
    cudaFuncSetAttribute(rnn_kernel, cudaFuncAttributeMaxDynamicSharedMemorySize,
                         (int)sizeof(Smem));
    rnn_kernel<<<NBLK, NTHR, sizeof(Smem)>>>(
        (const float*)d_in[0],
        (const float*)d_in[1],  (const float*)d_in[2],
        (const float*)d_in[3],  (const float*)d_in[4],
        (const float*)d_in[5],  (const float*)d_in[6],
        (const float*)d_in[7],  (const float*)d_in[8],
        (const float*)d_in[9],  (const float*)d_in[10],
        (const float*)d_in[11], (const float*)d_in[12],
        (const float*)d_in[13], (const float*)d_in[14],
        (float*)d_out);
}

// round 9
// speedup vs baseline: 2.0226x; 1.0005x over previous
#include <cuda_runtime.h>

// ---------------------------------------------------------------------------
// RNN_70480413327462: 59-step patch-grid RNN + 9-neighbor center attention.
// R8: 2D CTA tiles (4x8 patches, 128 CTAs x 32 warps). Q always from smem;
// K/V from smem for intra-tile neighbors (~78%), global for halo, selected
// by per-lane generic pointers. Flat global barrier. 1 warp = 1 patch.
// ---------------------------------------------------------------------------

#define NBLK   128
#define NTHR   1024
#define NWARPS 32
#define PP     4096
#define NROWS  8192
#define HH     32
#define TSTEPS 59
#define NOBS   10
#define KPAD   36
#define PPK    (PP * KPAD)
#define INV_SQRT_E 0.1714985851425088f   // 1/sqrt(34)

// double-buffered K/V scratch for halo exchange (step parity)
__device__ float g_K[2][NROWS * KPAD];
__device__ float g_V[2][NROWS * KPAD];
__device__ unsigned g_arrive = 0;
__device__ volatile unsigned g_gen = 0;

struct Smem {
    float4 Wc[32][17];        // c<8: W_x2h chunk c; c>=8: W_h2h chunk c-8
    float4 Wq[32][9];
    float4 Wk[32][9];
    float4 Wv[32][9];
    float4 Mw[32][9];         // (W_fcsa@W_out)^T chunks (9 used, tail zeroed)
    float4 Wf[32][9];         // W_fc2 chunks (8 used)
    float4 We[6][9];          // ext rows (q32,q33,k32,k33,v32,v33)
    float4 RB[NWARPS][2][17]; // per-warp stage: [0..8] inp/ht/o, [9..16] h
    float  sQ[64 * KPAD];     // tile q rows [slot*2+b]
    float  sK[64 * KPAD];
    float  sV[64 * KPAD];
    unsigned sbase;
};

__device__ __forceinline__ float warpAllSum(float v) {
#pragma unroll
    for (int o = 16; o > 0; o >>= 1) v += __shfl_xor_sync(0xffffffffu, v, o);
    return v;
}

__device__ __forceinline__ float ftanh(float x) {
    float e = __expf(2.f * x);
    return 1.f - __fdividef(2.f, e + 1.f);
}

__device__ __forceinline__ float dot4(float4 a, float4 b) {
    return fmaf(a.x, b.x, fmaf(a.y, b.y, fmaf(a.z, b.z, a.w * b.w)));
}

extern __shared__ unsigned char smem_raw[];

__global__ void __launch_bounds__(NTHR, 1) rnn_kernel(
    const float* __restrict__ x,
    const float* __restrict__ W_x2h, const float* __restrict__ b_x2h,
    const float* __restrict__ W_h2h, const float* __restrict__ b_h2h,
    const float* __restrict__ W_fc2, const float* __restrict__ b_fc2,
    const float* __restrict__ ln_g,  const float* __restrict__ ln_b,
    const float* __restrict__ W_fcsa,const float* __restrict__ b_fcsa,
    const float* __restrict__ W_in,  const float* __restrict__ b_in,
    const float* __restrict__ W_out, const float* __restrict__ b_out,
    float* __restrict__ out)
{
    Smem* sm = reinterpret_cast<Smem*>(smem_raw);
    const int tid = threadIdx.x;

    // ---------------- smem weight init ----------------
    for (int idx = tid; idx < 32 * 16; idx += NTHR) {
        int e = idx >> 4, c = idx & 15;
        const float* src = (c < 8) ? (W_x2h + e * 32 + c * 4)
                                   : (W_h2h + e * 32 + (c - 8) * 4);
        sm->Wc[e][c] = make_float4(src[0], src[1], src[2], src[3]);
    }
    for (int idx = tid; idx < 32 * 8; idx += NTHR) {
        int e = idx >> 3, c = idx & 7, i = c * 4;
        const float* q = W_in + e * 34 + i;
        const float* k = W_in + (34 + e) * 34 + i;
        const float* v = W_in + (68 + e) * 34 + i;
        const float* f = W_fc2 + e * 32 + i;
        sm->Wq[e][c] = make_float4(q[0], q[1], q[2], q[3]);
        sm->Wk[e][c] = make_float4(k[0], k[1], k[2], k[3]);
        sm->Wv[e][c] = make_float4(v[0], v[1], v[2], v[3]);
        sm->Wf[e][c] = make_float4(f[0], f[1], f[2], f[3]);
    }
    for (int idx = tid; idx < 32 * 9; idx += NTHR) {
        int e = idx / 9, c = idx % 9;
        float w[4];
#pragma unroll
        for (int d = 0; d < 4; d++) {
            int f = c * 4 + d;
            float acc = 0.f;
            if (f < 34)
                for (int g = 0; g < 34; g++)
                    acc += W_fcsa[e * 34 + g] * W_out[g * 34 + f];
            w[d] = acc;
        }
        sm->Mw[e][c] = make_float4(w[0], w[1], w[2], w[3]);
    }
    for (int idx = tid; idx < 6 * 8; idx += NTHR) {
        int j = idx >> 3, c = idx & 7;
        int row = (j >> 1) * 34 + 32 + (j & 1);
        const float* src = W_in + row * 34 + c * 4;
        sm->We[j][c] = make_float4(src[0], src[1], src[2], src[3]);
    }
    // zero smem q/k/v pads (elements 34,35 of every row)
    for (int idx = tid; idx < 64 * 2; idx += NTHR) {
        int row = idx >> 1, e = 34 + (idx & 1);
        sm->sQ[row * KPAD + e] = 0.f;
        sm->sK[row * KPAD + e] = 0.f;
        sm->sV[row * KPAD + e] = 0.f;
    }
    if (tid == 0) sm->sbase = g_gen;   // safe: no release before all CTAs arrive

    const int lane = tid & 31;
    const int wid  = tid >> 5;

    // 2D tile mapping: 16x8 CTA grid of 4x8 patch tiles; warp = patch in tile
    const int tr = blockIdx.x >> 3;        // 0..15
    const int tc = blockIdx.x & 7;         // 0..7
    const int pi = wid >> 3;               // 0..3 tile row
    const int pj = wid & 7;                // 0..7 tile col
    const int r  = tr * 4 + pi;
    const int cI = tc * 8 + pj;
    const int p  = r * 64 + cI;
    const int ownSlot = wid;

    // ---------------- per-lane constants ----------------
    const int sRow = lane >> 4;            // batch half
    const int sM   = lane & 15;
    const bool sAct = (sM < 9);
    const bool eAct = (sM < 6);

    float bql, bkl, bvl, bcombL, bfL, lngL, lnbL, bbL;
    float exC = 0.f;
    int   eoffG = 0;
    int   qOffS = 0;                       // smem float offset of q row
    const float* kPtrS = sm->sK;           // per-lane K source (static part)
    const float* vPtrS = sm->sV;
    int   kOffG = 0;                       // global offset when halo
    bool  intra = true;

    {
        float c0 = (float)r  * (1.f / 64.f);
        float c1 = (float)cI * (1.f / 64.f);
        int rc  = min(max(r, 1), 62);
        int ccn = min(max(cI, 1), 62);
        // query row: always inside own tile
        int qslot = (rc - tr * 4) * 8 + (ccn - tc * 8);
        qOffS = (qslot * 2 + sRow) * KPAD;
        if (sAct) {
            int nr = rc + sM / 3 - 1;
            int nc = ccn + sM % 3 - 1;
            intra = (nr >= tr * 4) && (nr < tr * 4 + 4) &&
                    (nc >= tc * 8) && (nc < tc * 8 + 8);
            if (intra) {
                int slot = (nr - tr * 4) * 8 + (nc - tc * 8);
                int off = (slot * 2 + sRow) * KPAD;
                kPtrS = sm->sK + off;
                vPtrS = sm->sV + off;
            } else {
                kOffG = (sRow * PP + nr * 64 + nc) * KPAD;
            }
        }

        bql = b_in[lane]      + c0 * W_in[lane * 34 + 32]      + c1 * W_in[lane * 34 + 33];
        bkl = b_in[34 + lane] + c0 * W_in[(34 + lane) * 34 + 32] + c1 * W_in[(34 + lane) * 34 + 33];
        bvl = b_in[68 + lane] + c0 * W_in[(68 + lane) * 34 + 32] + c1 * W_in[(68 + lane) * 34 + 33];
        bcombL = b_x2h[lane] + b_h2h[lane];
        bfL  = b_fc2[lane];
        lngL = ln_g[lane];
        lnbL = ln_b[lane];
        {
            float acc = b_fcsa[lane];
            for (int g = 0; g < 34; g++) acc += b_out[g] * W_fcsa[lane * 34 + g];
            bbL = acc;
        }
        if (eAct) {
            int row = (sM >> 1) * 34 + 32 + (sM & 1);
            exC = b_in[row] + c0 * W_in[row * 34 + 32] + c1 * W_in[row * 34 + 33];
            eoffG = (sRow * PP + p) * KPAD + 32 + (sM & 1);
        }
        // zero h staging + global K/V row pads (elements 34,35) once
        ((float*)sm->RB[wid][0])[36 + lane] = 0.f;
        ((float*)sm->RB[wid][1])[36 + lane] = 0.f;
        if (lane < 2) {
#pragma unroll
            for (int par = 0; par < 2; par++) {
#pragma unroll
                for (int row = 0; row < 2; row++) {
                    size_t o = (size_t)(row * PP + p) * KPAD + 34 + lane;
                    g_K[par][o] = 0.f; g_V[par][o] = 0.f;
                }
            }
        }
    }
    __syncthreads();

    const unsigned sbase = sm->sbase;
    const int r0Off = p * KPAD + lane;
    const int r1Off = (PP + p) * KPAD + lane;
    const int sOff0 = (ownSlot * 2 + 0) * KPAD + lane;
    const int sOff1 = (ownSlot * 2 + 1) * KPAD + lane;

    float4* RB0 = sm->RB[wid][0];
    float4* RB1 = sm->RB[wid][1];
    float*  RB0f = (float*)RB0;
    float*  RB1f = (float*)RB1;

    float h0 = 0.f, h1 = 0.f, ht0 = 0.f, ht1 = 0.f;

    for (int t = 0; t < TSTEPS; t++) {
        const int buf = t & 1;
        float* Kb = g_K[buf];
        float* Vb = g_V[buf];

        // protect smem q/k/v (phase2 of t-1 done before overwrite)
        __syncthreads();

        // =============== PHASE 1: RNN cell + QKV produce ===============
        {
            if (t < NOBS) {
                RB0f[lane] = x[((size_t)t * NROWS + p) * HH + lane];
                RB1f[lane] = x[((size_t)t * NROWS + PP + p) * HH + lane];
            }
            __syncwarp();

            float a0 = bcombL, a1 = bcombL;
#pragma unroll
            for (int c = 0; c < 16; c++) {
                float4 w  = sm->Wc[lane][c];
                int dc = (c < 8) ? c : c + 1;     // h lives at chunks 9..16
                a0 += dot4(RB0[dc], w);
                a1 += dot4(RB1[dc], w);
            }
            ht0 = ftanh(a0);
            ht1 = ftanh(a1);

            __syncwarp();
            RB0f[lane] = ht0;    // stage ht in chunks 0..7
            RB1f[lane] = ht1;
            __syncwarp();

            float q0 = bql, k0 = bkl, v0 = bvl;
            float q1 = bql, k1 = bkl, v1 = bvl;
#pragma unroll
            for (int c = 0; c < 8; c++) {
                float4 wq = sm->Wq[lane][c];
                float4 wk = sm->Wk[lane][c];
                float4 wv = sm->Wv[lane][c];
                float4 t0 = RB0[c];
                float4 t1 = RB1[c];
                q0 += dot4(t0, wq); k0 += dot4(t0, wk); v0 += dot4(t0, wv);
                q1 += dot4(t1, wq); k1 += dot4(t1, wk); v1 += dot4(t1, wv);
            }
            // smem (tile) copies
            sm->sQ[sOff0] = q0; sm->sK[sOff0] = k0; sm->sV[sOff0] = v0;
            sm->sQ[sOff1] = q1; sm->sK[sOff1] = k1; sm->sV[sOff1] = v1;
            // global copies for halo consumers (K/V only)
            Kb[r0Off] = k0; Vb[r0Off] = v0;
            Kb[r1Off] = k1; Vb[r1Off] = v1;

            // ext elements e=32,33: lanes 0-5 batch0, 16-21 batch1
            if (eAct) {
                const float4* htp = sRow ? RB1 : RB0;
                float ex = exC;
#pragma unroll
                for (int c = 0; c < 8; c++)
                    ex += dot4(htp[c], sm->We[sM][c]);
                int sExt = (ownSlot * 2 + sRow) * KPAD + 32 + (sM & 1);
                if (sM < 2) {
                    sm->sQ[sExt] = ex;
                } else if (sM < 4) {
                    sm->sK[sExt] = ex; Kb[eoffG] = ex;
                } else {
                    sm->sV[sExt] = ex; Vb[eoffG] = ex;
                }
            }
        }

        // =============== GRID BARRIER (one per step) ===============
        {
            __threadfence();
            __syncthreads();
            if (tid == 0) {
                unsigned want = sbase + (unsigned)t + 1u;
                unsigned tk = atomicAdd(&g_arrive, 1u);
                if ((tk % (unsigned)NBLK) == (unsigned)(NBLK - 1)) {
                    g_gen = want;                    // single releaser
                } else {
                    while ((int)(g_gen - want) < 0) __nanosleep(32);
                }
            }
            __syncthreads();
            __threadfence();
        }

        // =============== PHASE 2: attention + update + pred ===============
        {
            // per-lane K source: smem (intra) or global halo (generic ptrs)
            const float4* kp = intra ? (const float4*)kPtrS
                                     : (const float4*)(Kb + kOffG);
            const float4* vp = intra ? (const float4*)vPtrS
                                     : (const float4*)(Vb + kOffG);
            float sc = -3.4e38f;
            if (sAct) {
                const float4* qrow = (const float4*)(sm->sQ + qOffS);
                float d = 0.f;
#pragma unroll
                for (int c = 0; c < 9; c++) {
                    float4 qc = qrow[c];
                    float4 kc = kp[c];
                    d += dot4(qc, kc);
                }
                sc = d;
            }
            // group softmax over 9 within each 16-lane half
            float mx = sc;
#pragma unroll
            for (int o = 8; o > 0; o >>= 1)
                mx = fmaxf(mx, __shfl_xor_sync(0xffffffffu, mx, o, 16));
            float ew = __expf((sc - mx) * INV_SQRT_E);
            float ssum = ew;
#pragma unroll
            for (int o = 8; o > 0; o >>= 1)
                ssum += __shfl_xor_sync(0xffffffffu, ssum, o, 16);
            float wgt = ew * __fdividef(1.f, ssum);

            // V mix: lane c of each half accumulates o-chunk c
            unsigned long long vpu = (unsigned long long)vp;
            float4 o4 = make_float4(0.f, 0.f, 0.f, 0.f);
#pragma unroll
            for (int m = 0; m < 9; m++) {
                float wm = __shfl_sync(0xffffffffu, wgt, m, 16);
                unsigned long long pm = __shfl_sync(0xffffffffu, vpu, m, 16);
                if (sAct) {
                    float4 vv = ((const float4*)pm)[sM];
                    o4.x = fmaf(wm, vv.x, o4.x);
                    o4.y = fmaf(wm, vv.y, o4.y);
                    o4.z = fmaf(wm, vv.z, o4.z);
                    o4.w = fmaf(wm, vv.w, o4.w);
                }
            }
            if (sAct) (sRow ? RB1 : RB0)[sM] = o4;   // o chunks 0..8
            __syncwarp();

            // fused out-proj + fcsa: h = ht + o @ M^T + bb
            float d0 = bbL, d1 = bbL;
#pragma unroll
            for (int c = 0; c < 9; c++) {
                float4 wt = sm->Mw[lane][c];
                d0 += dot4(RB0[c], wt);
                d1 += dot4(RB1[c], wt);
            }
            h0 = ht0 + d0;
            h1 = ht1 + d1;

            RB0f[36 + lane] = h0;   // h chunks 9..16
            RB1f[36 + lane] = h1;
            __syncwarp();

            // fc2 + layernorm -> pred
            float y0 = bfL, y1 = bfL;
#pragma unroll
            for (int c = 0; c < 8; c++) {
                float4 wt = sm->Wf[lane][c];
                y0 += dot4(RB0[9 + c], wt);
                y1 += dot4(RB1[9 + c], wt);
            }
            float m0 = warpAllSum(y0) * (1.f / 32.f);
            float dd0 = y0 - m0;
            float var0 = warpAllSum(dd0 * dd0) * (1.f / 32.f);
            float pred0 = dd0 * rsqrtf(var0 + 1e-5f) * lngL + lnbL;
            float m1 = warpAllSum(y1) * (1.f / 32.f);
            float dd1 = y1 - m1;
            float var1 = warpAllSum(dd1 * dd1) * (1.f / 32.f);
            float pred1 = dd1 * rsqrtf(var1 + 1e-5f) * lngL + lnbL;

            RB0f[lane] = pred0;     // stage as next-step input (chunks 0..7)
            RB1f[lane] = pred1;

            out[((size_t)t * NROWS + p) * HH + lane]      = pred0;
            out[((size_t)t * NROWS + PP + p) * HH + lane] = pred1;
        }
    }
}

extern "C" void kernel_launch(void* const* d_in, const int* in_sizes, int n_in,
                              void* d_out, int out_size) {
    (void)in_sizes; (void)n_in; (void)out_size;
    cudaFuncSetAttribute(rnn_kernel, cudaFuncAttributeMaxDynamicSharedMemorySize,
                         (int)sizeof(Smem));
    rnn_kernel<<<NBLK, NTHR, sizeof(Smem)>>>(
        (const float*)d_in[0],
        (const float*)d_in[1],  (const float*)d_in[2],
        (const float*)d_in[3],  (const float*)d_in[4],
        (const float*)d_in[5],  (const float*)d_in[6],
        (const float*)d_in[7],  (const float*)d_in[8],
        (const float*)d_in[9],  (const float*)d_in[10],
        (const float*)d_in[11], (const float*)d_in[12],
        (const float*)d_in[13], (const float*)d_in[14],
        (float*)d_out);
}

// round 11
// speedup vs baseline: 2.1136x; 1.0450x over previous
#include <cuda_runtime.h>

// ---------------------------------------------------------------------------
// RNN_70480413327462: 59-step patch-grid RNN + 9-neighbor center attention.
// R9: R2 compute structure (best: 748us) + FENCE-FREE grid barrier using
// gpu-scope release/acquire atomics (no MEMBAR.GPU, no CCTL.IVALL L1 flush).
// ---------------------------------------------------------------------------

#define NBLK   148
#define NTHR   896
#define NWARPS 28
#define PP     4096
#define NROWS  8192
#define HH     32
#define TSTEPS 59
#define NOBS   10
#define KPAD   36
#define INV_SQRT_E 0.1714985851425088f   // 1/sqrt(34)

// double-buffered Q/K/V scratch (step parity), padded rows of 36 floats
__device__ float g_Q[2][NROWS * KPAD];
__device__ float g_K[2][NROWS * KPAD];
__device__ float g_V[2][NROWS * KPAD];
__device__ unsigned g_arrive = 0;
__device__ unsigned g_gen = 0;

__device__ __forceinline__ unsigned atomAddAcqRelGpu(unsigned* p, unsigned v) {
    unsigned old;
    asm volatile("atom.add.acq_rel.gpu.u32 %0, [%1], %2;"
                 : "=r"(old) : "l"(p), "r"(v) : "memory");
    return old;
}
__device__ __forceinline__ void stReleaseGpu(unsigned* p, unsigned v) {
    asm volatile("st.release.gpu.u32 [%0], %1;" :: "l"(p), "r"(v) : "memory");
}
__device__ __forceinline__ unsigned ldAcquireGpu(unsigned* p) {
    unsigned v;
    asm volatile("ld.acquire.gpu.u32 %0, [%1];" : "=r"(v) : "l"(p) : "memory");
    return v;
}

struct Smem {
    float4 Wc[32][17];        // c<8: W_x2h chunk c; c>=8: W_h2h chunk c-8
    float4 Wq[32][9];
    float4 Wk[32][9];
    float4 Wv[32][9];
    float4 Mw[32][9];         // (W_fcsa@W_out)^T chunks (9 used, tail zeroed)
    float4 Wf[32][9];         // W_fc2 chunks (8 used)
    float4 We[6][9];          // ext rows (q32,q33,k32,k33,v32,v33)
    float4 RB[NWARPS][2][17]; // per-warp stage: [0..8] inp/ht/o, [9..16] h
    int    NBS[NWARPS][12];   // 9 neighbor row-offsets (elements)
    unsigned sbase;
};

__device__ __forceinline__ float warpAllSum(float v) {
#pragma unroll
    for (int o = 16; o > 0; o >>= 1) v += __shfl_xor_sync(0xffffffffu, v, o);
    return v;
}

__device__ __forceinline__ float ftanh(float x) {
    float e = __expf(2.f * x);
    return 1.f - __fdividef(2.f, e + 1.f);
}

__device__ __forceinline__ float dot4(float4 a, float4 b) {
    return fmaf(a.x, b.x, fmaf(a.y, b.y, fmaf(a.z, b.z, a.w * b.w)));
}

extern __shared__ unsigned char smem_raw[];

__global__ void __launch_bounds__(NTHR, 1) rnn_kernel(
    const float* __restrict__ x,
    const float* __restrict__ W_x2h, const float* __restrict__ b_x2h,
    const float* __restrict__ W_h2h, const float* __restrict__ b_h2h,
    const float* __restrict__ W_fc2, const float* __restrict__ b_fc2,
    const float* __restrict__ ln_g,  const float* __restrict__ ln_b,
    const float* __restrict__ W_fcsa,const float* __restrict__ b_fcsa,
    const float* __restrict__ W_in,  const float* __restrict__ b_in,
    const float* __restrict__ W_out, const float* __restrict__ b_out,
    float* __restrict__ out)
{
    Smem* sm = reinterpret_cast<Smem*>(smem_raw);
    const int tid = threadIdx.x;

    // ---------------- smem weight init ----------------
    for (int idx = tid; idx < 32 * 16; idx += NTHR) {
        int e = idx >> 4, c = idx & 15;
        const float* src = (c < 8) ? (W_x2h + e * 32 + c * 4)
                                   : (W_h2h + e * 32 + (c - 8) * 4);
        sm->Wc[e][c] = make_float4(src[0], src[1], src[2], src[3]);
    }
    for (int idx = tid; idx < 32 * 8; idx += NTHR) {
        int e = idx >> 3, c = idx & 7, i = c * 4;
        const float* q = W_in + e * 34 + i;
        const float* k = W_in + (34 + e) * 34 + i;
        const float* v = W_in + (68 + e) * 34 + i;
        const float* f = W_fc2 + e * 32 + i;
        sm->Wq[e][c] = make_float4(q[0], q[1], q[2], q[3]);
        sm->Wk[e][c] = make_float4(k[0], k[1], k[2], k[3]);
        sm->Wv[e][c] = make_float4(v[0], v[1], v[2], v[3]);
        sm->Wf[e][c] = make_float4(f[0], f[1], f[2], f[3]);
    }
    for (int idx = tid; idx < 32 * 9; idx += NTHR) {
        int e = idx / 9, c = idx % 9;
        float w[4];
#pragma unroll
        for (int d = 0; d < 4; d++) {
            int f = c * 4 + d;
            float acc = 0.f;
            if (f < 34)
                for (int g = 0; g < 34; g++)
                    acc += W_fcsa[e * 34 + g] * W_out[g * 34 + f];
            w[d] = acc;
        }
        sm->Mw[e][c] = make_float4(w[0], w[1], w[2], w[3]);
    }
    for (int idx = tid; idx < 6 * 8; idx += NTHR) {
        int j = idx >> 3, c = idx & 7;
        int row = (j >> 1) * 34 + 32 + (j & 1);
        const float* src = W_in + row * 34 + c * 4;
        sm->We[j][c] = make_float4(src[0], src[1], src[2], src[3]);
    }
    if (tid == 0) sm->sbase = ldAcquireGpu(&g_gen);   // stable: no release till all arrive

    const int lane = tid & 31;
    const int wid  = tid >> 5;
    const int p    = blockIdx.x * NWARPS + wid;
    const bool active = (p < PP);

    // ---------------- per-lane constants ----------------
    int pqOff = 0;
    float bql = 0.f, bkl = 0.f, bvl = 0.f;
    float bcombL = 0.f, bfL = 0.f, lngL = 0.f, lnbL = 0.f, bbL = 0.f;
    float exC = 0.f;
    int   eoff = 0;
    const int sRow = lane >> 4;           // attention half: 0->batch0, 1->batch1
    const int sM   = lane & 15;           // per-half index
    const bool sAct = (sM < 9);
    const bool eAct = (sM < 6);

    if (active) {
        int r = p >> 6, cI = p & 63;
        float c0 = (float)r  * (1.f / 64.f);
        float c1 = (float)cI * (1.f / 64.f);
        int rc  = min(max(r, 1), 62);
        int ccn = min(max(cI, 1), 62);
        pqOff = (rc * 64 + ccn) * KPAD;
        if (lane < 9)
            sm->NBS[wid][lane] = ((rc + lane / 3 - 1) * 64 + (ccn + lane % 3 - 1)) * KPAD;

        bql = b_in[lane]      + c0 * W_in[lane * 34 + 32]      + c1 * W_in[lane * 34 + 33];
        bkl = b_in[34 + lane] + c0 * W_in[(34 + lane) * 34 + 32] + c1 * W_in[(34 + lane) * 34 + 33];
        bvl = b_in[68 + lane] + c0 * W_in[(68 + lane) * 34 + 32] + c1 * W_in[(68 + lane) * 34 + 33];
        bcombL = b_x2h[lane] + b_h2h[lane];
        bfL  = b_fc2[lane];
        lngL = ln_g[lane];
        lnbL = ln_b[lane];
        {
            float acc = b_fcsa[lane];
            for (int g = 0; g < 34; g++) acc += b_out[g] * W_fcsa[lane * 34 + g];
            bbL = acc;
        }
        if (eAct) {
            int j = sM;
            int row = (j >> 1) * 34 + 32 + (j & 1);
            exC = b_in[row] + c0 * W_in[row * 34 + 32] + c1 * W_in[row * 34 + 33];
            eoff = ((sRow ? PP + p : p)) * KPAD + 32 + (j & 1);
        }
        // zero h staging + QKV row pads (elements 34,35) once
        ((float*)sm->RB[wid][0])[36 + lane] = 0.f;
        ((float*)sm->RB[wid][1])[36 + lane] = 0.f;
        if (lane < 2) {
#pragma unroll
            for (int par = 0; par < 2; par++) {
#pragma unroll
                for (int row = 0; row < 2; row++) {
                    size_t o = (size_t)(row * PP + p) * KPAD + 34 + lane;
                    g_Q[par][o] = 0.f; g_K[par][o] = 0.f; g_V[par][o] = 0.f;
                }
            }
        }
    }
    __syncthreads();

    const unsigned sbase = sm->sbase;
    int nbBase = (active && sAct) ? sm->NBS[wid][sM] : 0;
    const int rowAdd = sRow * PP * KPAD;
    const int kOffR  = nbBase + rowAdd;
    const int qOffR  = pqOff + rowAdd;
    const int r0Off  = p * KPAD + lane;
    const int r1Off  = (PP + p) * KPAD + lane;

    float4* RB0 = sm->RB[wid][0];
    float4* RB1 = sm->RB[wid][1];
    float*  RB0f = (float*)RB0;
    float*  RB1f = (float*)RB1;

    float h0 = 0.f, h1 = 0.f, ht0 = 0.f, ht1 = 0.f;

    for (int t = 0; t < TSTEPS; t++) {
        const int buf = t & 1;
        float* Qb = g_Q[buf];
        float* Kb = g_K[buf];
        float* Vb = g_V[buf];

        // =============== PHASE 1: RNN cell + QKV produce ===============
        if (active) {
            if (t < NOBS) {   // stage external input (else pred already staged)
                RB0f[lane] = x[((size_t)t * NROWS + p) * HH + lane];
                RB1f[lane] = x[((size_t)t * NROWS + PP + p) * HH + lane];
            }
            __syncwarp();

            float a0 = bcombL, a1 = bcombL;
#pragma unroll
            for (int c = 0; c < 16; c++) {
                float4 w  = sm->Wc[lane][c];
                int dc = (c < 8) ? c : c + 1;     // h lives at chunks 9..16
                a0 += dot4(RB0[dc], w);
                a1 += dot4(RB1[dc], w);
            }
            ht0 = ftanh(a0);
            ht1 = ftanh(a1);

            __syncwarp();
            RB0f[lane] = ht0;    // stage ht in chunks 0..7 (overwrites inp)
            RB1f[lane] = ht1;
            __syncwarp();

            float q0 = bql, k0 = bkl, v0 = bvl;
            float q1 = bql, k1 = bkl, v1 = bvl;
#pragma unroll
            for (int c = 0; c < 8; c++) {
                float4 wq = sm->Wq[lane][c];
                float4 wk = sm->Wk[lane][c];
                float4 wv = sm->Wv[lane][c];
                float4 t0 = RB0[c];
                float4 t1 = RB1[c];
                q0 += dot4(t0, wq); k0 += dot4(t0, wk); v0 += dot4(t0, wv);
                q1 += dot4(t1, wq); k1 += dot4(t1, wk); v1 += dot4(t1, wv);
            }
            Qb[r0Off] = q0; Kb[r0Off] = k0; Vb[r0Off] = v0;
            Qb[r1Off] = q1; Kb[r1Off] = k1; Vb[r1Off] = v1;

            // extra elements e=32,33 of q/k/v: lanes 0-5 row0, 16-21 row1
            if (eAct) {
                const float4* htp = sRow ? RB1 : RB0;
                float ex = exC;
#pragma unroll
                for (int c = 0; c < 8; c++)
                    ex += dot4(htp[c], sm->We[sM][c]);
                float* eb = (sM < 2) ? Qb : ((sM < 4) ? Kb : Vb);
                eb[eoff] = ex;
            }
        }

        // =============== FENCE-FREE GRID BARRIER (one per step) ===============
        {
            __syncthreads();                       // intra-CTA: all stores issued
            if (tid == 0) {
                unsigned want = sbase + (unsigned)t + 1u;
                unsigned tk = atomAddAcqRelGpu(&g_arrive, 1u);
                if ((tk % (unsigned)NBLK) == (unsigned)(NBLK - 1)) {
                    stReleaseGpu(&g_gen, want);    // single releaser
                } else {
                    while ((int)(ldAcquireGpu(&g_gen) - want) < 0)
                        __nanosleep(16);
                }
            }
            __syncthreads();                       // broadcast acquire to all warps
        }

        // =============== PHASE 2: attention gather + update + pred ===============
        if (active) {
            // --- scores: lane m of each half computes q . k_nb[m] over 36 ---
            float sc = -3.4e38f;
            if (sAct) {
                const float4* qrow = (const float4*)(Qb + qOffR);
                const float4* krow = (const float4*)(Kb + kOffR);
                float d = 0.f;
#pragma unroll
                for (int c = 0; c < 9; c++) {
                    float4 qc = __ldcg(qrow + c);
                    float4 kc = __ldcg(krow + c);
                    d += dot4(qc, kc);
                }
                sc = d;
            }
            // group softmax over 9 within each 16-lane half
            float mx = sc;
#pragma unroll
            for (int o = 8; o > 0; o >>= 1)
                mx = fmaxf(mx, __shfl_xor_sync(0xffffffffu, mx, o, 16));
            float ew = __expf((sc - mx) * INV_SQRT_E);
            float ssum = ew;
#pragma unroll
            for (int o = 8; o > 0; o >>= 1)
                ssum += __shfl_xor_sync(0xffffffffu, ssum, o, 16);
            float wgt = ew * __fdividef(1.f, ssum);

            // --- V mix: lane c of each half accumulates o-chunk c ---
            float4 o4 = make_float4(0.f, 0.f, 0.f, 0.f);
#pragma unroll
            for (int m = 0; m < 9; m++) {
                float wm = __shfl_sync(0xffffffffu, wgt, m, 16);
                int   nm = __shfl_sync(0xffffffffu, nbBase, m, 16);
                if (sAct) {
                    float4 vv = __ldcg((const float4*)(Vb + nm + rowAdd) + sM);
                    o4.x = fmaf(wm, vv.x, o4.x);
                    o4.y = fmaf(wm, vv.y, o4.y);
                    o4.z = fmaf(wm, vv.z, o4.z);
                    o4.w = fmaf(wm, vv.w, o4.w);
                }
            }
            if (sAct) (sRow ? RB1 : RB0)[sM] = o4;   // o chunks 0..8
            __syncwarp();

            // --- fused out-proj + fcsa: h = ht + o @ M^T + bb ---
            float d0 = bbL, d1 = bbL;
#pragma unroll
            for (int c = 0; c < 9; c++) {
                float4 wt = sm->Mw[lane][c];
                d0 += dot4(RB0[c], wt);
                d1 += dot4(RB1[c], wt);
            }
            h0 = ht0 + d0;
            h1 = ht1 + d1;

            // stage h (chunks 9..16) for fc2 + next-step RNN
            RB0f[36 + lane] = h0;
            RB1f[36 + lane] = h1;
            __syncwarp();

            // --- fc2 + layernorm -> pred ---
            float y0 = bfL, y1 = bfL;
#pragma unroll
            for (int c = 0; c < 8; c++) {
                float4 wt = sm->Wf[lane][c];
                y0 += dot4(RB0[9 + c], wt);
                y1 += dot4(RB1[9 + c], wt);
            }
            float m0 = warpAllSum(y0) * (1.f / 32.f);
            float dd0 = y0 - m0;
            float var0 = warpAllSum(dd0 * dd0) * (1.f / 32.f);
            float pred0 = dd0 * rsqrtf(var0 + 1e-5f) * lngL + lnbL;
            float m1 = warpAllSum(y1) * (1.f / 32.f);
            float dd1 = y1 - m1;
            float var1 = warpAllSum(dd1 * dd1) * (1.f / 32.f);
            float pred1 = dd1 * rsqrtf(var1 + 1e-5f) * lngL + lnbL;

            // stage pred as next-step input (chunks 0..7)
            RB0f[lane] = pred0;
            RB1f[lane] = pred1;

            out[((size_t)t * NROWS + p) * HH + lane]      = pred0;
            out[((size_t)t * NROWS + PP + p) * HH + lane] = pred1;
        }
    }
}

extern "C" void kernel_launch(void* const* d_in, const int* in_sizes, int n_in,
                              void* d_out, int out_size) {
    (void)in_sizes; (void)n_in; (void)out_size;
    cudaFuncSetAttribute(rnn_kernel, cudaFuncAttributeMaxDynamicSharedMemorySize,
                         (int)sizeof(Smem));
    rnn_kernel<<<NBLK, NTHR, sizeof(Smem)>>>(
        (const float*)d_in[0],
        (const float*)d_in[1],  (const float*)d_in[2],
        (const float*)d_in[3],  (const float*)d_in[4],
        (const float*)d_in[5],  (const float*)d_in[6],
        (const float*)d_in[7],  (const float*)d_in[8],
        (const float*)d_in[9],  (const float*)d_in[10],
        (const float*)d_in[11], (const float*)d_in[12],
        (const float*)d_in[13], (const float*)d_in[14],
        (float*)d_out);
}

// round 15
// speedup vs baseline: 2.1177x; 1.0020x over previous
#include <cuda_runtime.h>

// ---------------------------------------------------------------------------
// RNN_70480413327462: 59-step patch-grid RNN + 9-neighbor center attention.
// R9: R2 compute structure (best: 748us) + FENCE-FREE grid barrier using
// gpu-scope release/acquire atomics (no MEMBAR.GPU, no CCTL.IVALL L1 flush).
// ---------------------------------------------------------------------------

#define NBLK   148
#define NTHR   896
#define NWARPS 28
#define PP     4096
#define NROWS  8192
#define HH     32
#define TSTEPS 59
#define NOBS   10
#define KPAD   36
#define INV_SQRT_E 0.1714985851425088f   // 1/sqrt(34)

// double-buffered Q/K/V scratch (step parity), padded rows of 36 floats
__device__ float g_Q[2][NROWS * KPAD];
__device__ float g_K[2][NROWS * KPAD];
__device__ float g_V[2][NROWS * KPAD];
__device__ unsigned g_arrive = 0;
__device__ unsigned g_gen = 0;

__device__ __forceinline__ unsigned atomAddAcqRelGpu(unsigned* p, unsigned v) {
    unsigned old;
    asm volatile("atom.add.acq_rel.gpu.u32 %0, [%1], %2;"
                 : "=r"(old) : "l"(p), "r"(v) : "memory");
    return old;
}
__device__ __forceinline__ void stReleaseGpu(unsigned* p, unsigned v) {
    asm volatile("st.release.gpu.u32 [%0], %1;" :: "l"(p), "r"(v) : "memory");
}
__device__ __forceinline__ unsigned ldAcquireGpu(unsigned* p) {
    unsigned v;
    asm volatile("ld.acquire.gpu.u32 %0, [%1];" : "=r"(v) : "l"(p) : "memory");
    return v;
}

struct Smem {
    float4 Wc[32][17];        // c<8: W_x2h chunk c; c>=8: W_h2h chunk c-8
    float4 Wq[32][9];
    float4 Wk[32][9];
    float4 Wv[32][9];
    float4 Mw[32][9];         // (W_fcsa@W_out)^T chunks (9 used, tail zeroed)
    float4 Wf[32][9];         // W_fc2 chunks (8 used)
    float4 We[6][9];          // ext rows (q32,q33,k32,k33,v32,v33)
    float4 RB[NWARPS][2][17]; // per-warp stage: [0..8] inp/ht/o, [9..16] h
    int    NBS[NWARPS][12];   // 9 neighbor row-offsets (elements)
    unsigned sbase;
};

__device__ __forceinline__ float warpAllSum(float v) {
#pragma unroll
    for (int o = 16; o > 0; o >>= 1) v += __shfl_xor_sync(0xffffffffu, v, o);
    return v;
}

__device__ __forceinline__ float ftanh(float x) {
    float e = __expf(2.f * x);
    return 1.f - __fdividef(2.f, e + 1.f);
}

__device__ __forceinline__ float dot4(float4 a, float4 b) {
    return fmaf(a.x, b.x, fmaf(a.y, b.y, fmaf(a.z, b.z, a.w * b.w)));
}

extern __shared__ unsigned char smem_raw[];

__global__ void __launch_bounds__(NTHR, 1) rnn_kernel(
    const float* __restrict__ x,
    const float* __restrict__ W_x2h, const float* __restrict__ b_x2h,
    const float* __restrict__ W_h2h, const float* __restrict__ b_h2h,
    const float* __restrict__ W_fc2, const float* __restrict__ b_fc2,
    const float* __restrict__ ln_g,  const float* __restrict__ ln_b,
    const float* __restrict__ W_fcsa,const float* __restrict__ b_fcsa,
    const float* __restrict__ W_in,  const float* __restrict__ b_in,
    const float* __restrict__ W_out, const float* __restrict__ b_out,
    float* __restrict__ out)
{
    Smem* sm = reinterpret_cast<Smem*>(smem_raw);
    const int tid = threadIdx.x;

    // ---------------- smem weight init ----------------
    for (int idx = tid; idx < 32 * 16; idx += NTHR) {
        int e = idx >> 4, c = idx & 15;
        const float* src = (c < 8) ? (W_x2h + e * 32 + c * 4)
                                   : (W_h2h + e * 32 + (c - 8) * 4);
        sm->Wc[e][c] = make_float4(src[0], src[1], src[2], src[3]);
    }
    for (int idx = tid; idx < 32 * 8; idx += NTHR) {
        int e = idx >> 3, c = idx & 7, i = c * 4;
        const float* q = W_in + e * 34 + i;
        const float* k = W_in + (34 + e) * 34 + i;
        const float* v = W_in + (68 + e) * 34 + i;
        const float* f = W_fc2 + e * 32 + i;
        sm->Wq[e][c] = make_float4(q[0], q[1], q[2], q[3]);
        sm->Wk[e][c] = make_float4(k[0], k[1], k[2], k[3]);
        sm->Wv[e][c] = make_float4(v[0], v[1], v[2], v[3]);
        sm->Wf[e][c] = make_float4(f[0], f[1], f[2], f[3]);
    }
    for (int idx = tid; idx < 32 * 9; idx += NTHR) {
        int e = idx / 9, c = idx % 9;
        float w[4];
#pragma unroll
        for (int d = 0; d < 4; d++) {
            int f = c * 4 + d;
            float acc = 0.f;
            if (f < 34)
                for (int g = 0; g < 34; g++)
                    acc += W_fcsa[e * 34 + g] * W_out[g * 34 + f];
            w[d] = acc;
        }
        sm->Mw[e][c] = make_float4(w[0], w[1], w[2], w[3]);
    }
    for (int idx = tid; idx < 6 * 8; idx += NTHR) {
        int j = idx >> 3, c = idx & 7;
        int row = (j >> 1) * 34 + 32 + (j & 1);
        const float* src = W_in + row * 34 + c * 4;
        sm->We[j][c] = make_float4(src[0], src[1], src[2], src[3]);
    }
    if (tid == 0) sm->sbase = ldAcquireGpu(&g_gen);   // stable: no release till all arrive

    const int lane = tid & 31;
    const int wid  = tid >> 5;
    const int p    = blockIdx.x * NWARPS + wid;
    const bool active = (p < PP);

    // ---------------- per-lane constants ----------------
    int pqOff = 0;
    float bql = 0.f, bkl = 0.f, bvl = 0.f;
    float bcombL = 0.f, bfL = 0.f, lngL = 0.f, lnbL = 0.f, bbL = 0.f;
    float exC = 0.f;
    int   eoff = 0;
    const int sRow = lane >> 4;           // attention half: 0->batch0, 1->batch1
    const int sM   = lane & 15;           // per-half index
    const bool sAct = (sM < 9);
    const bool eAct = (sM < 6);

    if (active) {
        int r = p >> 6, cI = p & 63;
        float c0 = (float)r  * (1.f / 64.f);
        float c1 = (float)cI * (1.f / 64.f);
        int rc  = min(max(r, 1), 62);
        int ccn = min(max(cI, 1), 62);
        pqOff = (rc * 64 + ccn) * KPAD;
        if (lane < 9)
            sm->NBS[wid][lane] = ((rc + lane / 3 - 1) * 64 + (ccn + lane % 3 - 1)) * KPAD;

        bql = b_in[lane]      + c0 * W_in[lane * 34 + 32]      + c1 * W_in[lane * 34 + 33];
        bkl = b_in[34 + lane] + c0 * W_in[(34 + lane) * 34 + 32] + c1 * W_in[(34 + lane) * 34 + 33];
        bvl = b_in[68 + lane] + c0 * W_in[(68 + lane) * 34 + 32] + c1 * W_in[(68 + lane) * 34 + 33];
        bcombL = b_x2h[lane] + b_h2h[lane];
        bfL  = b_fc2[lane];
        lngL = ln_g[lane];
        lnbL = ln_b[lane];
        {
            float acc = b_fcsa[lane];
            for (int g = 0; g < 34; g++) acc += b_out[g] * W_fcsa[lane * 34 + g];
            bbL = acc;
        }
        if (eAct) {
            int j = sM;
            int row = (j >> 1) * 34 + 32 + (j & 1);
            exC = b_in[row] + c0 * W_in[row * 34 + 32] + c1 * W_in[row * 34 + 33];
            eoff = ((sRow ? PP + p : p)) * KPAD + 32 + (j & 1);
        }
        // zero h staging + QKV row pads (elements 34,35) once
        ((float*)sm->RB[wid][0])[36 + lane] = 0.f;
        ((float*)sm->RB[wid][1])[36 + lane] = 0.f;
        if (lane < 2) {
#pragma unroll
            for (int par = 0; par < 2; par++) {
#pragma unroll
                for (int row = 0; row < 2; row++) {
                    size_t o = (size_t)(row * PP + p) * KPAD + 34 + lane;
                    g_Q[par][o] = 0.f; g_K[par][o] = 0.f; g_V[par][o] = 0.f;
                }
            }
        }
    }
    __syncthreads();

    const unsigned sbase = sm->sbase;
    int nbBase = (active && sAct) ? sm->NBS[wid][sM] : 0;
    const int rowAdd = sRow * PP * KPAD;
    const int kOffR  = nbBase + rowAdd;
    const int qOffR  = pqOff + rowAdd;
    const int r0Off  = p * KPAD + lane;
    const int r1Off  = (PP + p) * KPAD + lane;

    float4* RB0 = sm->RB[wid][0];
    float4* RB1 = sm->RB[wid][1];
    float*  RB0f = (float*)RB0;
    float*  RB1f = (float*)RB1;

    float h0 = 0.f, h1 = 0.f, ht0 = 0.f, ht1 = 0.f;

    for (int t = 0; t < TSTEPS; t++) {
        const int buf = t & 1;
        float* Qb = g_Q[buf];
        float* Kb = g_K[buf];
        float* Vb = g_V[buf];

        // =============== PHASE 1: RNN cell + QKV produce ===============
        if (active) {
            if (t < NOBS) {   // stage external input (else pred already staged)
                RB0f[lane] = x[((size_t)t * NROWS + p) * HH + lane];
                RB1f[lane] = x[((size_t)t * NROWS + PP + p) * HH + lane];
            }
            __syncwarp();

            float a0 = bcombL, a1 = bcombL;
#pragma unroll
            for (int c = 0; c < 16; c++) {
                float4 w  = sm->Wc[lane][c];
                int dc = (c < 8) ? c : c + 1;     // h lives at chunks 9..16
                a0 += dot4(RB0[dc], w);
                a1 += dot4(RB1[dc], w);
            }
            ht0 = ftanh(a0);
            ht1 = ftanh(a1);

            __syncwarp();
            RB0f[lane] = ht0;    // stage ht in chunks 0..7 (overwrites inp)
            RB1f[lane] = ht1;
            __syncwarp();

            float q0 = bql, k0 = bkl, v0 = bvl;
            float q1 = bql, k1 = bkl, v1 = bvl;
#pragma unroll
            for (int c = 0; c < 8; c++) {
                float4 wq = sm->Wq[lane][c];
                float4 wk = sm->Wk[lane][c];
                float4 wv = sm->Wv[lane][c];
                float4 t0 = RB0[c];
                float4 t1 = RB1[c];
                q0 += dot4(t0, wq); k0 += dot4(t0, wk); v0 += dot4(t0, wv);
                q1 += dot4(t1, wq); k1 += dot4(t1, wk); v1 += dot4(t1, wv);
            }
            Qb[r0Off] = q0; Kb[r0Off] = k0; Vb[r0Off] = v0;
            Qb[r1Off] = q1; Kb[r1Off] = k1; Vb[r1Off] = v1;

            // extra elements e=32,33 of q/k/v: lanes 0-5 row0, 16-21 row1
            if (eAct) {
                const float4* htp = sRow ? RB1 : RB0;
                float ex = exC;
#pragma unroll
                for (int c = 0; c < 8; c++)
                    ex += dot4(htp[c], sm->We[sM][c]);
                float* eb = (sM < 2) ? Qb : ((sM < 4) ? Kb : Vb);
                eb[eoff] = ex;
            }
        }

        // =============== FENCE-FREE GRID BARRIER (one per step) ===============
        {
            __syncthreads();                       // intra-CTA: all stores issued
            if (tid == 0) {
                unsigned want = sbase + (unsigned)t + 1u;
                unsigned tk = atomAddAcqRelGpu(&g_arrive, 1u);
                if ((tk % (unsigned)NBLK) == (unsigned)(NBLK - 1)) {
                    stReleaseGpu(&g_gen, want);    // single releaser
                } else {
                    while ((int)(ldAcquireGpu(&g_gen) - want) < 0)
                        __nanosleep(16);
                }
            }
            __syncthreads();                       // broadcast acquire to all warps
        }

        // =============== PHASE 2: attention gather + update + pred ===============
        if (active) {
            // --- scores: lane m of each half computes q . k_nb[m] over 36 ---
            float sc = -3.4e38f;
            if (sAct) {
                const float4* qrow = (const float4*)(Qb + qOffR);
                const float4* krow = (const float4*)(Kb + kOffR);
                float d = 0.f;
#pragma unroll
                for (int c = 0; c < 9; c++) {
                    float4 qc = __ldcg(qrow + c);
                    float4 kc = __ldcg(krow + c);
                    d += dot4(qc, kc);
                }
                sc = d;
            }
            // group softmax over 9 within each 16-lane half
            float mx = sc;
#pragma unroll
            for (int o = 8; o > 0; o >>= 1)
                mx = fmaxf(mx, __shfl_xor_sync(0xffffffffu, mx, o, 16));
            float ew = __expf((sc - mx) * INV_SQRT_E);
            float ssum = ew;
#pragma unroll
            for (int o = 8; o > 0; o >>= 1)
                ssum += __shfl_xor_sync(0xffffffffu, ssum, o, 16);
            float wgt = ew * __fdividef(1.f, ssum);

            // --- V mix: lane c of each half accumulates o-chunk c ---
            float4 o4 = make_float4(0.f, 0.f, 0.f, 0.f);
#pragma unroll
            for (int m = 0; m < 9; m++) {
                float wm = __shfl_sync(0xffffffffu, wgt, m, 16);
                int   nm = __shfl_sync(0xffffffffu, nbBase, m, 16);
                if (sAct) {
                    float4 vv = __ldcg((const float4*)(Vb + nm + rowAdd) + sM);
                    o4.x = fmaf(wm, vv.x, o4.x);
                    o4.y = fmaf(wm, vv.y, o4.y);
                    o4.z = fmaf(wm, vv.z, o4.z);
                    o4.w = fmaf(wm, vv.w, o4.w);
                }
            }
            if (sAct) (sRow ? RB1 : RB0)[sM] = o4;   // o chunks 0..8
            __syncwarp();

            // --- fused out-proj + fcsa: h = ht + o @ M^T + bb ---
            float d0 = bbL, d1 = bbL;
#pragma unroll
            for (int c = 0; c < 9; c++) {
                float4 wt = sm->Mw[lane][c];
                d0 += dot4(RB0[c], wt);
                d1 += dot4(RB1[c], wt);
            }
            h0 = ht0 + d0;
            h1 = ht1 + d1;

            // stage h (chunks 9..16) for fc2 + next-step RNN
            RB0f[36 + lane] = h0;
            RB1f[36 + lane] = h1;
            __syncwarp();

            // --- fc2 + layernorm -> pred ---
            float y0 = bfL, y1 = bfL;
#pragma unroll
            for (int c = 0; c < 8; c++) {
                float4 wt = sm->Wf[lane][c];
                y0 += dot4(RB0[9 + c], wt);
                y1 += dot4(RB1[9 + c], wt);
            }
            float m0 = warpAllSum(y0) * (1.f / 32.f);
            float dd0 = y0 - m0;
            float var0 = warpAllSum(dd0 * dd0) * (1.f / 32.f);
            float pred0 = dd0 * rsqrtf(var0 + 1e-5f) * lngL + lnbL;
            float m1 = warpAllSum(y1) * (1.f / 32.f);
            float dd1 = y1 - m1;
            float var1 = warpAllSum(dd1 * dd1) * (1.f / 32.f);
            float pred1 = dd1 * rsqrtf(var1 + 1e-5f) * lngL + lnbL;

            // stage pred as next-step input (chunks 0..7)
            RB0f[lane] = pred0;
            RB1f[lane] = pred1;

            out[((size_t)t * NROWS + p) * HH + lane]      = pred0;
            out[((size_t)t * NROWS + PP + p) * HH + lane] = pred1;
        }
    }
}

extern "C" void kernel_launch(void* const* d_in, const int* in_sizes, int n_in,
                              void* d_out, int out_size) {
    (void)in_sizes; (void)n_in; (void)out_size;
    cudaFuncSetAttribute(rnn_kernel, cudaFuncAttributeMaxDynamicSharedMemorySize,
                         (int)sizeof(Smem));
    rnn_kernel<<<NBLK, NTHR, sizeof(Smem)>>>(
        (const float*)d_in[0],
        (const float*)d_in[1],  (const float*)d_in[2],
        (const float*)d_in[3],  (const float*)d_in[4],
        (const float*)d_in[5],  (const float*)d_in[6],
        (const float*)d_in[7],  (const float*)d_in[8],
        (const float*)d_in[9],  (const float*)d_in[10],
        (const float*)d_in[11], (const float*)d_in[12],
        (const float*)d_in[13], (const float*)d_in[14],
        (float*)d_out);
}